// round 15
// baseline (speedup 1.0000x reference)
#include <cuda_runtime.h>

// Problem constants (from reference: B, S, D = 16, 4096, 512)
#define BB 16
#define SS 4096
#define DD 512
#define SLICES 9   // gather blocks per batch; each rescans its batch (32KB)

// ---------------------------------------------------------------------------
// Sync-free fused kernel. Grid = (SLICES, BB) = 144 blocks x 1024 threads
// (1 block/SM; occupancy is block-count-limited, so registers are free).
// Phase A: block (slice, b) redundantly scans batch b's keep flags into an
//   SMEM rank table (stable block-wide exclusive scan, 4 elems/thread),
//   then writes its slice of the mask row vectorized (off the hot loop).
// Phase B: block gathers its contiguous slice of batch b's output rows,
//   TWO rows per warp iteration with all 8 LDG.128 front-batched (MLP=8;
//   clean re-test of R3 now that occupancy can't collapse). Indices come
//   from SMEM — no global index-load dependency chain.
// ---------------------------------------------------------------------------
__global__ void __launch_bounds__(1024)
fused_kernel(const float* __restrict__ x,
             const float4* __restrict__ probs4,
             const float4* __restrict__ uniform4,
             float* __restrict__ out_padded,
             float* __restrict__ out_mask,
             int max_length) {
    const int b     = blockIdx.y;
    const int slice = blockIdx.x;
    const int t     = threadIdx.x;
    const int lane  = t & 31;
    const int warp  = t >> 5;

    __shared__ int s_src[SS];      // rank -> source element index (16KB)
    __shared__ int warp_sums[32];
    __shared__ int s_count;

    // ---------------- Phase A: scan batch b into SMEM ----------------
    const int idx4 = b * (SS / 4) + t;
    float4 p = probs4[idx4];
    float4 u = uniform4[idx4];

    int keep[4];
    keep[0] = (u.x >= p.x) ? 1 : 0;
    keep[1] = (u.y >= p.y) ? 1 : 0;
    keep[2] = (u.z >= p.z) ? 1 : 0;
    keep[3] = (u.w >= p.w) ? 1 : 0;
    const int local = keep[0] + keep[1] + keep[2] + keep[3];

    int v = local;
#pragma unroll
    for (int o = 1; o < 32; o <<= 1) {
        int uu = __shfl_up_sync(0xffffffffu, v, o);
        if (lane >= o) v += uu;
    }
    if (lane == 31) warp_sums[warp] = v;
    __syncthreads();
    if (warp == 0) {
        int w = warp_sums[lane];
#pragma unroll
        for (int o = 1; o < 32; o <<= 1) {
            int uu = __shfl_up_sync(0xffffffffu, w, o);
            if (lane >= o) w += uu;
        }
        warp_sums[lane] = w;
        if (lane == 31) s_count = w;
    }
    __syncthreads();

    const int excl = v - local + (warp > 0 ? warp_sums[warp - 1] : 0);

    int r = excl;
#pragma unroll
    for (int i = 0; i < 4; i++) {
        if (keep[i]) {
            s_src[r] = t * 4 + i;
            r++;
        }
    }
    __syncthreads();

    // ---------------- Slice bounds + vectorized mask write ----------------
    const int count = s_count;
    const int chunk = (max_length + SLICES - 1) / SLICES;
    const int jbeg  = slice * chunk;
    int jend = jbeg + chunk;
    if (jend > max_length) jend = max_length;

    const float* xb = x + (long long)b * SS * DD;
    float* outb     = out_padded + (long long)b * max_length * DD;
    float* maskb    = out_mask + (long long)b * max_length;

    for (int j = jbeg + t; j < jend; j += 1024) {
        maskb[j] = (j < count) ? 1.0f : 0.0f;
    }

    // ---------------- Phase B: gather, 2 rows per warp iteration ----------------
    const float4 z = make_float4(0.f, 0.f, 0.f, 0.f);

    for (int j0 = jbeg + warp; j0 < jend; j0 += 64) {
        const int j1 = j0 + 32;
        const bool has1 = (j1 < jend);
        const bool k0 = (j0 < count);
        const bool k1 = has1 && (j1 < count);

        float4 v0 = z, v1 = z, v2 = z, v3 = z;
        float4 w0 = z, w1 = z, w2 = z, w3 = z;

        if (k0) {
            const float4* src = reinterpret_cast<const float4*>(
                xb + (long long)s_src[j0] * DD);
            v0 = __ldcg(src + lane);
            v1 = __ldcg(src + lane + 32);
            v2 = __ldcg(src + lane + 64);
            v3 = __ldcg(src + lane + 96);
        }
        if (k1) {
            const float4* src = reinterpret_cast<const float4*>(
                xb + (long long)s_src[j1] * DD);
            w0 = __ldcg(src + lane);
            w1 = __ldcg(src + lane + 32);
            w2 = __ldcg(src + lane + 64);
            w3 = __ldcg(src + lane + 96);
        }

        float4* d0 = reinterpret_cast<float4*>(outb + (long long)j0 * DD);
        __stcs(d0 + lane,      v0);
        __stcs(d0 + lane + 32, v1);
        __stcs(d0 + lane + 64, v2);
        __stcs(d0 + lane + 96, v3);
        if (has1) {
            float4* d1 = reinterpret_cast<float4*>(outb + (long long)j1 * DD);
            __stcs(d1 + lane,      w0);
            __stcs(d1 + lane + 32, w1);
            __stcs(d1 + lane + 64, w2);
            __stcs(d1 + lane + 96, w3);
        }
    }
}

// ---------------------------------------------------------------------------
// Launch: out_size = B*ML*(D+1)  =>  ML = out_size / (B*(D+1))
// Single kernel node, no device-side synchronization anywhere.
// ---------------------------------------------------------------------------
extern "C" void kernel_launch(void* const* d_in, const int* in_sizes, int n_in,
                              void* d_out, int out_size) {
    const float* x       = (const float*)d_in[0];
    const float* probs   = (const float*)d_in[1];
    const float* uniform = (const float*)d_in[2];
    float* out = (float*)d_out;

    const int max_length = out_size / (BB * (DD + 1));
    float* out_mask = out + (long long)BB * max_length * DD;

    dim3 grid(SLICES, BB);
    fused_kernel<<<grid, 1024>>>(x, (const float4*)probs,
                                 (const float4*)uniform,
                                 out, out_mask, max_length);
}

// round 16
// speedup vs baseline: 1.0244x; 1.0244x over previous
#include <cuda_runtime.h>

// Problem constants (from reference: B, S, D = 16, 4096, 512)
#define BB 16
#define SS 4096
#define DD 512
#define SLICES 9   // gather blocks per batch; each rescans its batch (32KB)

// ---------------------------------------------------------------------------
// Sync-free fused kernel. Grid = (SLICES, BB) = 144 blocks, 1024 threads.
// Phase A: block (slice, b) redundantly scans batch b's keep flags into an
//   SMEM rank table (stable block-wide exclusive scan, 4 elems/thread).
//   No global scratch, no inter-block communication, no barriers beyond
//   one __syncthreads.
// Phase B: block gathers its contiguous slice of batch b's output rows,
//   warp-per-row, 4x LDG.128 front-batched -> 4x STG.128; padding rows
//   write zeros; lane 0 writes the mask element. The gather sits on the
//   memory-system floor (~136.5MB compulsory traffic + 4.6MB rescan
//   redundancy at ~6.7TB/s effective L2 throughput ≈ 20.1us).
// ---------------------------------------------------------------------------
__global__ void __launch_bounds__(1024)
fused_kernel(const float* __restrict__ x,
             const float4* __restrict__ probs4,
             const float4* __restrict__ uniform4,
             float* __restrict__ out_padded,
             float* __restrict__ out_mask,
             int max_length) {
    const int b     = blockIdx.y;
    const int slice = blockIdx.x;
    const int t     = threadIdx.x;
    const int lane  = t & 31;
    const int warp  = t >> 5;

    __shared__ int s_src[SS];      // rank -> source element index (16KB)
    __shared__ int warp_sums[32];
    __shared__ int s_count;

    // ---------------- Phase A: scan batch b into SMEM ----------------
    const int idx4 = b * (SS / 4) + t;
    float4 p = probs4[idx4];
    float4 u = uniform4[idx4];

    int keep[4];
    keep[0] = (u.x >= p.x) ? 1 : 0;
    keep[1] = (u.y >= p.y) ? 1 : 0;
    keep[2] = (u.z >= p.z) ? 1 : 0;
    keep[3] = (u.w >= p.w) ? 1 : 0;
    const int local = keep[0] + keep[1] + keep[2] + keep[3];

    int v = local;
#pragma unroll
    for (int o = 1; o < 32; o <<= 1) {
        int uu = __shfl_up_sync(0xffffffffu, v, o);
        if (lane >= o) v += uu;
    }
    if (lane == 31) warp_sums[warp] = v;
    __syncthreads();
    if (warp == 0) {
        int w = warp_sums[lane];
#pragma unroll
        for (int o = 1; o < 32; o <<= 1) {
            int uu = __shfl_up_sync(0xffffffffu, w, o);
            if (lane >= o) w += uu;
        }
        warp_sums[lane] = w;
        if (lane == 31) s_count = w;
    }
    __syncthreads();

    const int excl = v - local + (warp > 0 ? warp_sums[warp - 1] : 0);

    int r = excl;
#pragma unroll
    for (int i = 0; i < 4; i++) {
        if (keep[i]) {
            s_src[r] = t * 4 + i;
            r++;
        }
    }
    __syncthreads();

    // ---------------- Phase B: gather this block's row slice ----------------
    const int count = s_count;
    const int chunk = (max_length + SLICES - 1) / SLICES;
    const int jbeg  = slice * chunk;
    int jend = jbeg + chunk;
    if (jend > max_length) jend = max_length;

    for (int j = jbeg + warp; j < jend; j += 32) {
        const long long row = (long long)b * max_length + j;
        float4* dst = reinterpret_cast<float4*>(out_padded + row * DD);

        if (j < count) {
            const int s = s_src[j];
            const float4* src = reinterpret_cast<const float4*>(
                x + ((long long)b * SS + s) * DD);
            float4 v0 = __ldcg(src + lane);
            float4 v1 = __ldcg(src + lane + 32);
            float4 v2 = __ldcg(src + lane + 64);
            float4 v3 = __ldcg(src + lane + 96);
            __stcs(dst + lane,      v0);
            __stcs(dst + lane + 32, v1);
            __stcs(dst + lane + 64, v2);
            __stcs(dst + lane + 96, v3);
        } else {
            const float4 z = make_float4(0.f, 0.f, 0.f, 0.f);
            __stcs(dst + lane,      z);
            __stcs(dst + lane + 32, z);
            __stcs(dst + lane + 64, z);
            __stcs(dst + lane + 96, z);
        }

        if (lane == 0) {
            out_mask[row] = (j < count) ? 1.0f : 0.0f;
        }
    }
}

// ---------------------------------------------------------------------------
// Launch: out_size = B*ML*(D+1)  =>  ML = out_size / (B*(D+1))
// Single kernel node, no device-side synchronization anywhere.
// ---------------------------------------------------------------------------
extern "C" void kernel_launch(void* const* d_in, const int* in_sizes, int n_in,
                              void* d_out, int out_size) {
    const float* x       = (const float*)d_in[0];
    const float* probs   = (const float*)d_in[1];
    const float* uniform = (const float*)d_in[2];
    float* out = (float*)d_out;

    const int max_length = out_size / (BB * (DD + 1));
    float* out_mask = out + (long long)BB * max_length * DD;

    dim3 grid(SLICES, BB);
    fused_kernel<<<grid, 1024>>>(x, (const float4*)probs,
                                 (const float4*)uniform,
                                 out, out_mask, max_length);
}